// round 17
// baseline (speedup 1.0000x reference)
#include <cuda_runtime.h>
#include <cuda_fp16.h>
#include <cstdint>

// ---------------------------------------------------------------------------
// Problem constants
// ---------------------------------------------------------------------------
#define BB    4
#define SEQ   2048
#define EMB   1024
#define NH    16
#define HD    64
#define MTOT  8192
#define NQKV  3072
#define KDIM  1024

// Q pre-scale: 0.125 (softmax scale) * log2(e)  -> S-mma output is log2-domain
#define QSCL  0.1803368801111137f

// ---------------------------------------------------------------------------
// Scratch (device globals, fp16; allocation-free)
// Packed-A (per [mtile][kchunk32], 4096 halfs = 512 uint4):
//   [mb 0..7][s 0..1][lane] uint4 = m16n8k16 A-frag
// Packed-B (per [ntile256][kchunk32], 8192 halfs = 2048 uint2):
//   [nb 0..31][s 0..1][lane] uint2 = m16n8k16 B-frag (nb-major)
// g_qh/g_kh: [bh][n][d] half.  g_vh: [bh][ktile][d 64][kv 128] half (transposed)
// ---------------------------------------------------------------------------
__device__ __half g_xph[(size_t)64 * 32 * 4096];
__device__ __half g_wqkvph[(size_t)12 * 32 * 8192];
__device__ __half g_woutph[(size_t)4 * 32 * 8192];
__device__ __half g_attph[(size_t)64 * 32 * 4096];
__device__ __half g_qh[(size_t)64 * SEQ * HD];
__device__ __half g_kh[(size_t)64 * SEQ * HD];
__device__ __half g_vh[(size_t)64 * 16 * HD * 128];

// ---------------------------------------------------------------------------
// Helpers
// ---------------------------------------------------------------------------
__device__ __forceinline__ uint32_t h2u(float a, float b) {
    __half2 h = __floats2half2_rn(a, b);
    return *(uint32_t*)&h;
}

// half2 2^x (one MUFU op for two elements)
__device__ __forceinline__ uint32_t ex2_h2(float a, float b) {
    __half2 h = __floats2half2_rn(a, b);
    uint32_t u = *(uint32_t*)&h;
    uint32_t r;
    asm volatile("ex2.approx.f16x2 %0, %1;" : "=r"(r) : "r"(u));
    return r;
}

__device__ __forceinline__ void mma16(float& c0, float& c1, float& c2, float& c3,
                                      uint32_t a0, uint32_t a1, uint32_t a2, uint32_t a3,
                                      uint32_t b0, uint32_t b1) {
    asm volatile(
        "mma.sync.aligned.m16n8k16.row.col.f32.f16.f16.f32 "
        "{%0,%1,%2,%3}, {%4,%5,%6,%7}, {%8,%9}, {%0,%1,%2,%3};"
        : "+f"(c0), "+f"(c1), "+f"(c2), "+f"(c3)
        : "r"(a0), "r"(a1), "r"(a2), "r"(a3), "r"(b0), "r"(b1));
}

__device__ __forceinline__ void cpa16(void* dst, const void* src) {
    uint32_t d = (uint32_t)__cvta_generic_to_shared(dst);
    asm volatile("cp.async.cg.shared.global [%0], [%1], 16;" :: "r"(d), "l"(src));
}
__device__ __forceinline__ void cpa_commit() {
    asm volatile("cp.async.commit_group;");
}
template <int N>
__device__ __forceinline__ void cpa_wait() {
    asm volatile("cp.async.wait_group %0;" :: "n"(N));
}

// ---------------------------------------------------------------------------
// Pack kernels (fp32 -> fp16 fragment-major)
// ---------------------------------------------------------------------------
__global__ __launch_bounds__(256)
void pack_a_h(const float* __restrict__ src, __half* __restrict__ dst) {
    __shared__ float ts[128][33];
    const int kc = blockIdx.x, mt = blockIdx.y;
    const int t = threadIdx.x;
#pragma unroll
    for (int j = 0; j < 4; j++) {
        int idx = t + j * 256;
        int r = idx >> 3, c4 = (idx & 7) * 4;
        float4 v = *(const float4*)(src + (size_t)(mt * 128 + r) * KDIM + kc * 32 + c4);
        ts[r][c4 + 0] = v.x; ts[r][c4 + 1] = v.y;
        ts[r][c4 + 2] = v.z; ts[r][c4 + 3] = v.w;
    }
    __syncthreads();
    uint4* out = (uint4*)(dst + ((size_t)mt * 32 + kc) * 4096);
#pragma unroll
    for (int j = 0; j < 2; j++) {
        int o = t + j * 256;                 // 0..511
        int mb = o >> 6, s = (o >> 5) & 1, lane = o & 31;
        int lr = lane >> 2, lc = lane & 3;
        int R = mb * 16, C = s * 16;
        uint4 v;
        v.x = h2u(ts[R + lr][C + 2 * lc], ts[R + lr][C + 2 * lc + 1]);
        v.y = h2u(ts[R + lr + 8][C + 2 * lc], ts[R + lr + 8][C + 2 * lc + 1]);
        v.z = h2u(ts[R + lr][C + 2 * lc + 8], ts[R + lr][C + 2 * lc + 9]);
        v.w = h2u(ts[R + lr + 8][C + 2 * lc + 8], ts[R + lr + 8][C + 2 * lc + 9]);
        out[o] = v;
    }
}

__global__ __launch_bounds__(256)
void pack_b_h(const float* __restrict__ src, __half* __restrict__ dst, int N) {
    __shared__ float ts[32][257];
    const int kc = blockIdx.x, ntile = blockIdx.y;
    const int t = threadIdx.x;
#pragma unroll
    for (int j = 0; j < 8; j++) {
        int idx = t + j * 256;
        int r = idx >> 6, c4 = (idx & 63) * 4;
        float4 v = *(const float4*)(src + (size_t)(kc * 32 + r) * N + ntile * 256 + c4);
        ts[r][c4 + 0] = v.x; ts[r][c4 + 1] = v.y;
        ts[r][c4 + 2] = v.z; ts[r][c4 + 3] = v.w;
    }
    __syncthreads();
    uint2* out = (uint2*)(dst + ((size_t)ntile * 32 + kc) * 8192);
#pragma unroll
    for (int j = 0; j < 8; j++) {
        int o = t + j * 256;                 // 0..2047
        int nb = o >> 6, s = (o >> 5) & 1, lane = o & 31;
        int lr = lane >> 2, lc = lane & 3;
        int K = s * 16, Nc = nb * 8 + lr;
        uint2 v;
        v.x = h2u(ts[K + 2 * lc][Nc], ts[K + 2 * lc + 1][Nc]);
        v.y = h2u(ts[K + 2 * lc + 8][Nc], ts[K + 2 * lc + 9][Nc]);
        out[o] = v;
    }
}

// ---------------------------------------------------------------------------
// fp16 GEMM, 2 CTAs/SM, 3-stage pipeline: CTA tile 128x128, 256 thr,
// warps 2(m) x 4(n), warp tile 64x32. K-chunk 64, 96 KB smem/CTA.
// wait<1> at boundary -> consumed stage resident one full chunk early.
// MODE 0: C = acc + bias (fp32) ; MODE 1: scatter q/k (half) + v (half, T)
// ---------------------------------------------------------------------------
#define STAGE_HALFS 16384             // A 8192 + B 8192
#define GSTAGES 3
#define PG_SMEM (GSTAGES * STAGE_HALFS * 2)   // 98304 bytes

template <int MODE>
__global__ __launch_bounds__(256, 2)
void gemm_h(const __half* __restrict__ Ap, const __half* __restrict__ Bp,
            const float* __restrict__ bias, float* __restrict__ C, int N) {
    extern __shared__ __half smp[];
    const int t = threadIdx.x;
    const int lane = t & 31;
    const int warp = t >> 5;
    const int wm = warp >> 2;       // 0..1
    const int wn = warp & 3;        // 0..3
    const int lr = lane >> 2;
    const int lc = lane & 3;
    const int mtile = blockIdx.y;
    const int ntile = blockIdx.x;          // 128-wide
    const int nt256 = ntile >> 1;
    const int nhalf = ntile & 1;

    float acc[4][4][4];
#pragma unroll
    for (int mt = 0; mt < 4; mt++)
#pragma unroll
        for (int nt = 0; nt < 4; nt++)
#pragma unroll
            for (int e = 0; e < 4; e++) acc[mt][nt][e] = 0.f;

    auto fill = [&](int sbuf, int c64) {
        __half* as = smp + sbuf * STAGE_HALFS;
        __half* bs = as + 8192;
        const __half* ga = Ap + ((size_t)mtile * 32 + c64 * 2) * 4096;
#pragma unroll
        for (int j = 0; j < 4; j++) {
            int i = t + j * 256;
            cpa16(as + i * 8, ga + i * 8);
        }
#pragma unroll
        for (int h = 0; h < 2; h++) {
            const __half* gb = Bp + ((size_t)nt256 * 32 + c64 * 2 + h) * 8192
                               + (size_t)nhalf * 4096;
#pragma unroll
            for (int j = 0; j < 2; j++) {
                int i = t + j * 256;
                cpa16(bs + h * 4096 + i * 8, gb + i * 8);
            }
        }
    };

    fill(0, 0); cpa_commit();
    fill(1, 1); cpa_commit();

    for (int c = 0; c < 16; c++) {
        if (c + 1 < 16) cpa_wait<1>(); else cpa_wait<0>();
        __syncthreads();
        if (c + 2 < 16) {
            fill((c + 2) % GSTAGES, c + 2);
            cpa_commit();
        }

        const __half* as = smp + (c % GSTAGES) * STAGE_HALFS;
        const __half* bs = as + 8192;

#pragma unroll
        for (int sub = 0; sub < 4; sub++) {
            const int c32l = sub >> 1, sh = sub & 1;
            uint4 a4[4];
            uint2 b2[4];
#pragma unroll
            for (int mt = 0; mt < 4; mt++)
                a4[mt] = *(const uint4*)(as + c32l * 4096 +
                    ((wm * 4 + mt) * 2 + sh) * 256 + lane * 8);
#pragma unroll
            for (int nt = 0; nt < 4; nt++)
                b2[nt] = *(const uint2*)(bs + c32l * 4096 +
                    (wn * 4 + nt) * 256 + sh * 128 + lane * 4);
#pragma unroll
            for (int mt = 0; mt < 4; mt++) {
#pragma unroll
                for (int nt = 0; nt < 4; nt++)
                    mma16(acc[mt][nt][0], acc[mt][nt][1], acc[mt][nt][2], acc[mt][nt][3],
                          a4[mt].x, a4[mt].y, a4[mt].z, a4[mt].w,
                          b2[nt].x, b2[nt].y);
            }
        }
    }

    // --- epilogue ---
#pragma unroll
    for (int mt = 0; mt < 4; mt++) {
#pragma unroll
        for (int nt = 0; nt < 4; nt++) {
            int r = mtile * 128 + wm * 64 + mt * 16 + lr;
            int c = ntile * 128 + wn * 32 + nt * 8 + 2 * lc;
            float e0 = acc[mt][nt][0], e1 = acc[mt][nt][1];
            float e2 = acc[mt][nt][2], e3 = acc[mt][nt][3];
            if (MODE == 0) {
                float b0 = bias[c], b1 = bias[c + 1];
                *(float2*)&C[(size_t)r * N + c] = make_float2(e0 + b0, e1 + b1);
                *(float2*)&C[(size_t)(r + 8) * N + c] = make_float2(e2 + b0, e3 + b1);
            } else {
                int which = c >> 10;
                int rr = c & 1023;
                int h = rr >> 6, d = rr & 63;
                int b = r >> 11, n = r & 2047;
                int bh = b * NH + h;
                if (which == 0) {
                    size_t off = ((size_t)bh * SEQ + n) * HD + d;
                    *(__half2*)&g_qh[off] = __floats2half2_rn(e0 * QSCL, e1 * QSCL);
                    *(__half2*)&g_qh[off + 8 * HD] =
                        __floats2half2_rn(e2 * QSCL, e3 * QSCL);
                } else if (which == 1) {
                    size_t off = ((size_t)bh * SEQ + n) * HD + d;
                    *(__half2*)&g_kh[off] = __floats2half2_rn(e0, e1);
                    *(__half2*)&g_kh[off + 8 * HD] = __floats2half2_rn(e2, e3);
                } else {
                    int ktile = n >> 7, kv = n & 127;
                    size_t vb = (((size_t)bh * 16 + ktile) * HD + d) * 128 + kv;
                    g_vh[vb]       = __float2half_rn(e0);   // (d,   kv)
                    g_vh[vb + 128] = __float2half_rn(e1);   // (d+1, kv)
                    g_vh[vb + 8]   = __float2half_rn(e2);   // (d,   kv+8)
                    g_vh[vb + 136] = __float2half_rn(e3);   // (d+1, kv+8)
                }
            }
        }
    }
}

// ---------------------------------------------------------------------------
// Flash attention fp16 v4: 256 thr, 2 CTAs/SM. Q tile 128, KV tile 128
// processed as two 64-wide halves (accS 32 regs -> fits 128-reg budget).
// No-max log2-domain softmax (Q pre-scaled by 0.125*log2e), P =
// ex2.approx.f16x2, row sums via ones-column mma. V pre-transposed [d][kv].
// ---------------------------------------------------------------------------
#define SQH 72
#define SKH 72
#define SVH 136
#define ATTN_SMEM_BYTES ((2 * 128 * SKH + 2 * 64 * SVH + 128 * SQH) * 2)

__global__ __launch_bounds__(256, 2)
void attn_kernel() {
    extern __shared__ __half smh[];
    __half* sKb = smh;                       // [2][128*SKH]
    __half* sVb = smh + 2 * 128 * SKH;       // [2][64*SVH] (V^T tiles)
    __half* sQ  = sVb + 2 * 64 * SVH;        // [128*SQH]

    const int t = threadIdx.x;
    const int lane = t & 31;
    const int warp = t >> 5;       // 0..7
    const int lr = lane >> 2;
    const int lc = lane & 3;
    const int rb = warp * 16;
    const int bh = blockIdx.y;
    const int q0 = blockIdx.x * 128;
    const size_t base = (size_t)bh * SEQ * HD;
    const uint32_t ONES2 = 0x3C003C00u;      // half2(1,1)

    auto kvload = [&](int s, int kt) {
        __half* dk = sKb + s * 128 * SKH;
        __half* dv = sVb + s * 64 * SVH;
        const __half* gk = g_kh + base + (size_t)kt * 128 * HD;
        const __half* gv = g_vh + ((size_t)bh * 16 + kt) * (HD * 128);
#pragma unroll
        for (int j = 0; j < 4; j++) {
            int i = t + j * 256;
            int rk = i >> 3, ck = (i & 7) * 8;
            cpa16(dk + rk * SKH + ck, gk + rk * HD + ck);
            int rv = i >> 4, cv = (i & 15) * 8;
            cpa16(dv + rv * SVH + cv, gv + rv * 128 + cv);
        }
    };

    // stage Q (128 x 64 half)
#pragma unroll
    for (int j = 0; j < 4; j++) {
        int i = t + j * 256;
        int r = i >> 3, c8 = (i & 7) * 8;
        cpa16(sQ + r * SQH + c8, g_qh + base + (size_t)(q0 + r) * HD + c8);
    }
    cpa_commit();
    kvload(0, 0);
    cpa_commit();
    cpa_wait<1>();      // Q resident
    __syncthreads();

    uint32_t qf[4][4];
#pragma unroll
    for (int s = 0; s < 4; s++) {
        qf[s][0] = *(const uint32_t*)&sQ[(rb + lr) * SQH + 16 * s + 2 * lc];
        qf[s][1] = *(const uint32_t*)&sQ[(rb + lr + 8) * SQH + 16 * s + 2 * lc];
        qf[s][2] = *(const uint32_t*)&sQ[(rb + lr) * SQH + 16 * s + 2 * lc + 8];
        qf[s][3] = *(const uint32_t*)&sQ[(rb + lr + 8) * SQH + 16 * s + 2 * lc + 8];
    }

    float accO[8][4];
    float accSum[4] = {0.f, 0.f, 0.f, 0.f};
#pragma unroll
    for (int nt = 0; nt < 8; nt++)
#pragma unroll
        for (int e = 0; e < 4; e++) accO[nt][e] = 0.f;

    for (int kt = 0; kt < SEQ / 128; kt++) {
        const int s = kt & 1;
        if (kt + 1 < SEQ / 128) {
            kvload(s ^ 1, kt + 1);
            cpa_commit();
            cpa_wait<1>();
        } else {
            cpa_wait<0>();
        }
        __syncthreads();

        const __half* sKs = sKb + s * 128 * SKH;
        const __half* sVs = sVb + s * 64 * SVH;

        // ---- two 64-wide KV halves: S-mma then fused ex2+O-mma ----
#pragma unroll
        for (int hf = 0; hf < 2; hf++) {
            float accS[8][4];
#pragma unroll
            for (int nt = 0; nt < 8; nt++)
#pragma unroll
                for (int e = 0; e < 4; e++) accS[nt][e] = 0.f;

#pragma unroll
            for (int nt = 0; nt < 8; nt++) {
                const int kvr = (hf * 8 + nt) * 8 + lr;
#pragma unroll
                for (int ks = 0; ks < 4; ks++) {
                    uint32_t b0 = *(const uint32_t*)&sKs[kvr * SKH + 16 * ks + 2 * lc];
                    uint32_t b1 = *(const uint32_t*)&sKs[kvr * SKH + 16 * ks + 2 * lc + 8];
                    mma16(accS[nt][0], accS[nt][1], accS[nt][2], accS[nt][3],
                          qf[ks][0], qf[ks][1], qf[ks][2], qf[ks][3], b0, b1);
                }
            }

#pragma unroll
            for (int g2 = 0; g2 < 4; g2++) {
                const int g = hf * 4 + g2;
                uint32_t a0 = ex2_h2(accS[2 * g2][0], accS[2 * g2][1]);
                uint32_t a1 = ex2_h2(accS[2 * g2][2], accS[2 * g2][3]);
                uint32_t a2 = ex2_h2(accS[2 * g2 + 1][0], accS[2 * g2 + 1][1]);
                uint32_t a3 = ex2_h2(accS[2 * g2 + 1][2], accS[2 * g2 + 1][3]);
#pragma unroll
                for (int nt = 0; nt < 8; nt++) {
                    uint32_t b0 = *(const uint32_t*)&sVs[(nt * 8 + lr) * SVH + 16 * g + 2 * lc];
                    uint32_t b1 = *(const uint32_t*)&sVs[(nt * 8 + lr) * SVH + 16 * g + 2 * lc + 8];
                    mma16(accO[nt][0], accO[nt][1], accO[nt][2], accO[nt][3],
                          a0, a1, a2, a3, b0, b1);
                }
                // row-sum via ones column (identical P as fed to V)
                mma16(accSum[0], accSum[1], accSum[2], accSum[3],
                      a0, a1, a2, a3, ONES2, ONES2);
            }
        }
        __syncthreads();
    }

    // ---- normalize & store to g_attph in packed-A half layout ----
    const int b = bh >> 4;
    const int h = bh & 15;
    const float i0 = 1.f / accSum[0], i1 = 1.f / accSum[2];
    const int mtile = (b * SEQ + q0) >> 7;
    const int mb = warp;

#pragma unroll
    for (int nt = 0; nt < 8; nt++) {
        int c32 = h * 2 + (nt >> 2);
        int sh = (nt >> 1) & 1;
        int sel = nt & 1;
        size_t base8 = ((((size_t)mtile * 32 + c32) * 8 + mb) * 2 + sh) * 256
                       + (lr * 4 + lc) * 8 + sel * 4;
        *(__half2*)&g_attph[base8] =
            __floats2half2_rn(accO[nt][0] * i0, accO[nt][1] * i0);
        *(__half2*)&g_attph[base8 + 2] =
            __floats2half2_rn(accO[nt][2] * i1, accO[nt][3] * i1);
    }
}

// ---------------------------------------------------------------------------
// Launch
// ---------------------------------------------------------------------------
extern "C" void kernel_launch(void* const* d_in, const int* in_sizes, int n_in,
                              void* d_out, int out_size) {
    const float* x    = (const float*)d_in[0];
    const float* Wqkv = (const float*)d_in[1];
    const float* Wout = (const float*)d_in[2];
    const float* bout = (const float*)d_in[3];
    float* out = (float*)d_out;

    static bool attr_done = false;
    if (!attr_done) {
        cudaFuncSetAttribute((const void*)gemm_h<1>,
                             cudaFuncAttributeMaxDynamicSharedMemorySize, PG_SMEM);
        cudaFuncSetAttribute((const void*)gemm_h<0>,
                             cudaFuncAttributeMaxDynamicSharedMemorySize, PG_SMEM);
        cudaFuncSetAttribute((const void*)attn_kernel,
                             cudaFuncAttributeMaxDynamicSharedMemorySize, ATTN_SMEM_BYTES);
        attr_done = true;
    }

    void* pxp = nullptr;  cudaGetSymbolAddress(&pxp, g_xph);
    void* pwq = nullptr;  cudaGetSymbolAddress(&pwq, g_wqkvph);
    void* pwo = nullptr;  cudaGetSymbolAddress(&pwo, g_woutph);
    void* patt = nullptr; cudaGetSymbolAddress(&patt, g_attph);

    // 0) pack + round inputs into fp16 fragment-major layouts
    pack_a_h<<<dim3(KDIM / 32, MTOT / 128), 256>>>(x, (__half*)pxp);
    pack_b_h<<<dim3(KDIM / 32, NQKV / 256), 256>>>(Wqkv, (__half*)pwq, NQKV);
    pack_b_h<<<dim3(KDIM / 32, EMB / 256), 256>>>(Wout, (__half*)pwo, EMB);

    // 1) QKV projection (fp16 mma, 128x128 tiles, 2 CTA/SM, 3-stage)
    gemm_h<1><<<dim3(NQKV / 128, MTOT / 128), 256, PG_SMEM>>>(
        (const __half*)pxp, (const __half*)pwq, nullptr, nullptr, NQKV);

    // 2) flash attention (2 CTA/SM, no-max softmax, mma row-sums)
    attn_kernel<<<dim3(SEQ / 128, BB * NH), 256, ATTN_SMEM_BYTES>>>();

    // 3) output projection + bias (fp16 mma, 128x128 tiles, 2 CTA/SM, 3-stage)
    gemm_h<0><<<dim3(EMB / 128, MTOT / 128), 256, PG_SMEM>>>(
        (const __half*)patt, (const __half*)pwo, bout, out, EMB);
}